// round 12
// baseline (speedup 1.0000x reference)
#include <cuda_runtime.h>
#include <math.h>
#include <stdint.h>

// Problem shapes (fixed for this bench)
#define BB 4
#define TT 512
#define SS 1024
#define HH 768
#define VV 50257

// Copy kernel: TWO CTAs per (b,t) row (R6 shape — fastest measured).
#define VLO1   25129                 // half0 = [0,25129), half1 = [25129,50257)
#define VPADH  25136                 // pad(<=3) + 25129, rounded up
#define SMEM_BYTES  (VPADH * 4)
#define NTHR 1024

#define NROWS (BB * TT)              // 2048
#define NU    (BB * SS)              // 4096 u rows
#define NUV   (NU + NROWS)           // 6144 projection rows

// Collapsed p_gen projections (produced by prep, consumed by pgen kernel).
__device__ float g_u[NU];
__device__ float g_v[NROWS];

// ---------------------------------------------------------------------------
// Kernel A (side stream): projections u[b,s]=src.W1, v[row]=tgt.W2+bias.
// One warp per row, 6144 rows.
// ---------------------------------------------------------------------------
__global__ void pgen_prep_kernel(const float* __restrict__ src,
                                 const float* __restrict__ tgt,
                                 const float* __restrict__ W,
                                 const float* __restrict__ bias)
{
    const int warp = (blockIdx.x * blockDim.x + threadIdx.x) >> 5;
    const int lane = threadIdx.x & 31;
    if (warp >= NUV) return;

    const float4* x;
    const float4* w;
    if (warp < NU) {
        x = reinterpret_cast<const float4*>(src + (size_t)warp * HH);
        w = reinterpret_cast<const float4*>(W);
    } else {
        x = reinterpret_cast<const float4*>(tgt + (size_t)(warp - NU) * HH);
        w = reinterpret_cast<const float4*>(W + HH);
    }
    float acc = 0.f;
    #pragma unroll
    for (int j = lane; j < HH / 4; j += 32) {
        float4 a = x[j], b = w[j];
        acc += a.x * b.x + a.y * b.y + a.z * b.z + a.w * b.w;
    }
    #pragma unroll
    for (int o = 16; o; o >>= 1) acc += __shfl_xor_sync(0xffffffffu, acc, o);
    if (lane == 0) {
        if (warp < NU) g_u[warp] = acc;
        else           g_v[warp - NU] = acc + bias[0];
    }
}

// ---------------------------------------------------------------------------
// Kernel B (side stream): p_gen[row] = sigmoid(attn[row,:].u[b,:] + v[row]).
// One warp per row, 2048 rows.
// ---------------------------------------------------------------------------
__global__ void pgen_row_kernel(const float* __restrict__ attn,
                                float* __restrict__ out_pgen)
{
    const int row  = (blockIdx.x * blockDim.x + threadIdx.x) >> 5;
    const int lane = threadIdx.x & 31;
    if (row >= NROWS) return;
    const int b = row >> 9;

    const float4* ar = reinterpret_cast<const float4*>(attn + (size_t)row * SS);
    const float4* ur = reinterpret_cast<const float4*>(g_u + b * SS);
    float acc = 0.f;
    #pragma unroll
    for (int j = lane; j < SS / 4; j += 32) {
        float4 a = ar[j], u = ur[j];
        acc += a.x * u.x + a.y * u.y + a.z * u.z + a.w * u.w;
    }
    #pragma unroll
    for (int o = 16; o; o >>= 1) acc += __shfl_xor_sync(0xffffffffu, acc, o);
    if (lane == 0) {
        const float zv = acc + g_v[row];
        out_pgen[row] = 1.f / (1.f + __expf(-zv));
    }
}

// ---------------------------------------------------------------------------
// Kernel C (main stream): PURE copy. Two CTAs per (b,t) row, each owning half
// the vocab: zero ~100KB smem accumulator, shared-atomic scatter, one TMA
// bulk-store. No pgen logic, no polls, minimal registers.
// ---------------------------------------------------------------------------
__global__ __launch_bounds__(NTHR, 2)
void copy_logits_kernel(const int* __restrict__ ids,
                        const float* __restrict__ attn,
                        float* __restrict__ out_logits)
{
    extern __shared__ float sm[];          // [VPADH] accumulator
    const int row  = blockIdx.x >> 1;      // b*T + t
    const int half = blockIdx.x & 1;
    const int b    = row >> 9;
    const int tid  = threadIdx.x;

    const int lo = half ? VLO1 : 0;
    const int hi = half ? VV   : VLO1;
    const int n  = hi - lo;

    // Global destination of this half-row; 16B phase decides head & pad.
    float* dst = out_logits + (size_t)row * VV + lo;
    const int head = (int)(((16u - ((uint32_t)(uintptr_t)dst & 15u)) & 15u) >> 2);
    const int pad  = (4 - head) & 3;       // sm[pad+head] is 16B-aligned

    // Phase 1: zero the accumulator (vectorized STS.128).
    float4* sm4 = reinterpret_cast<float4*>(sm);
    const float4 z4 = make_float4(0.f, 0.f, 0.f, 0.f);
    #pragma unroll
    for (int i = tid; i < VPADH / 4; i += NTHR) sm4[i] = z4;
    __syncthreads();

    // Phase 2: range-predicated scatter-add. Exactly S=1024 threads, 1 each.
    const float a  = attn[(size_t)row * SS + tid];
    const int   id = ids[b * SS + tid];
    if (id >= lo && id < hi) atomicAdd(&sm[pad + id - lo], a);
    __syncthreads();                       // all atomics complete

    // Phase 3: head/tail scalars + one bulk-async (TMA) copy for the middle.
    const int nvec = (n - head) >> 2;
    const int tail = head + 4 * nvec;

    if (tid < head)     __stcs(dst + tid, sm[pad + tid]);
    if (tid < n - tail) __stcs(dst + tail + tid, sm[pad + tail + tid]);

    if (tid == 0) {
        asm volatile("fence.proxy.async.shared::cta;" ::: "memory");
        uint32_t saddr;
        asm("{ .reg .u64 t; cvta.to.shared.u64 t, %1; cvt.u32.u64 %0, t; }"
            : "=r"(saddr) : "l"(sm + pad + head));
        asm volatile(
            "cp.async.bulk.global.shared::cta.bulk_group [%0], [%1], %2;"
            :: "l"(dst + head), "r"(saddr), "r"(16 * nvec) : "memory");
        asm volatile("cp.async.bulk.commit_group;" ::: "memory");
        asm volatile("cp.async.bulk.wait_group 0;" ::: "memory");
    }
}

// ---------------------------------------------------------------------------
// Launch: fork a side stream inside the capture so the tiny pgen chain
// (prep -> pgen) runs CONCURRENTLY with the DRAM-bound copy kernel.
// Stream/events created once on the first (non-capturing) call.
// ---------------------------------------------------------------------------
extern "C" void kernel_launch(void* const* d_in, const int* in_sizes, int n_in,
                              void* d_out, int out_size)
{
    const int*   ids  = (const int*)  d_in[0];  // [B,S] int32
    const float* attn = (const float*)d_in[1];  // [B,T,S]
    const float* src  = (const float*)d_in[2];  // [B,S,H]
    const float* tgt  = (const float*)d_in[3];  // [B,T,H]
    const float* W    = (const float*)d_in[4];  // [2H,1]
    const float* bias = (const float*)d_in[5];  // [1]

    float* out_pgen   = (float*)d_out;              // [B,T]  (first output)
    float* out_logits = out_pgen + (size_t)BB * TT; // [B,T,V]

    cudaFuncSetAttribute(copy_logits_kernel,
                         cudaFuncAttributeMaxDynamicSharedMemorySize,
                         SMEM_BYTES);

    static cudaStream_t s2 = 0;
    static cudaEvent_t  evF = 0, evJ = 0;
    static int init_state = 0;             // 0=untried, 1=ok, -1=failed
    if (init_state == 0) {
        if (cudaStreamCreateWithFlags(&s2, cudaStreamNonBlocking) == cudaSuccess &&
            cudaEventCreateWithFlags(&evF, cudaEventDisableTiming) == cudaSuccess &&
            cudaEventCreateWithFlags(&evJ, cudaEventDisableTiming) == cudaSuccess)
            init_state = 1;
        else {
            init_state = -1;
            (void)cudaGetLastError();
        }
    }

    if (init_state == 1) {
        // Fork: side stream joins the capture via the event dependency.
        cudaEventRecord(evF, 0);
        cudaStreamWaitEvent(s2, evF, 0);

        pgen_prep_kernel<<<(NUV + 7) / 8, 256, 0, s2>>>(src, tgt, W, bias);
        pgen_row_kernel<<<(NROWS + 7) / 8, 256, 0, s2>>>(attn, out_pgen);
        cudaEventRecord(evJ, s2);

        // Main stream: pure copy kernel, concurrent with the side chain.
        copy_logits_kernel<<<NROWS * 2, NTHR, SMEM_BYTES>>>(ids, attn,
                                                            out_logits);
        // Join before kernel_launch returns.
        cudaStreamWaitEvent(0, evJ, 0);
    } else {
        // Serial fallback (R7 shape without PDL).
        pgen_prep_kernel<<<(NUV + 7) / 8, 256>>>(src, tgt, W, bias);
        pgen_row_kernel<<<(NROWS + 7) / 8, 256>>>(attn, out_pgen);
        copy_logits_kernel<<<NROWS * 2, NTHR, SMEM_BYTES>>>(ids, attn,
                                                            out_logits);
    }
}